// round 9
// baseline (speedup 1.0000x reference)
#include <cuda_runtime.h>

// Problem: B=2, C=32, H=80, W=240, D=64 (MAXDISP=192, D=192/3)
// out shape (B, 2C, D, H, W) fp32:
//   left  (c2 <  32): out = x[b,c2,h,w]        * (w >= d)
//   right (c2 >= 32): out = y[b,c2-32,h,w-d]   * (w >= d)
//
// 629 MB of stores, ~10 MB of (heavily reused, L2-resident) loads.
// Pure store-BW bound; R8 = 94.4 us (6.66 TB/s write stream, DRAM 74.5%,
// L2 62.3%) with __stcs + 4 float4/thread. Store-MLP ladder saturated.
//
// This round's single change: __stcs -> __stwt (st.global.wt) on the output
// stream. The output is write-only and never re-read; write-through skips
// the L2 streaming-allocation transit that the profile shows at 62% busy.
// A/B probe: everything else identical to R8.

#define BN 2
#define CN 32
#define HN 80
#define WN 240
#define DN 64
#define W4 (WN / 4)                               // 60 float4 per row
#define TOTAL4 (BN * 2 * CN * DN * HN * W4)       // 39,321,600 = 38400 * 1024

__device__ __forceinline__ float4 compute_elem(
    const float* __restrict__ x, const float* __restrict__ y, unsigned int i)
{
    // i -> (row, w4); row -> (b, c2, d, h), h fastest
    unsigned int row = i / W4;                    // magic-number div
    unsigned int w4  = i - row * W4;
    unsigned int h   = row % HN;                  // magic-number mod
    unsigned int t   = row / HN;
    unsigned int d   = t & (DN - 1);   t >>= 6;
    unsigned int c2  = t & (2 * CN - 1);
    unsigned int b   = t >> 6;

    int w0 = (int)(w4 * 4);
    int di = (int)d;
    float4 v;

    if (c2 < CN) {
        // left: aligned float4 load from x, mask lanes where w < d
        const float4* xr = reinterpret_cast<const float4*>(
            x + (((b * CN + c2) * HN + h) * WN));
        v = __ldg(xr + w4);
        if (w0 < di) {
            v.x = (w0     >= di) ? v.x : 0.0f;
            v.y = (w0 + 1 >= di) ? v.y : 0.0f;
            v.z = (w0 + 2 >= di) ? v.z : 0.0f;
            v.w = (w0 + 3 >= di) ? v.w : 0.0f;
        }
    } else {
        // right: y[b, c, h, w - d]; scalar loads (misaligned by d), y is
        // fully L2-resident (4.9 MB, 64x reuse) so latency is hidden.
        unsigned int c = c2 - CN;
        const float* yr = y + (((b * CN + c) * HN + h) * WN);
        v.x = (w0     >= di) ? __ldg(yr + (w0     - di)) : 0.0f;
        v.y = (w0 + 1 >= di) ? __ldg(yr + (w0 + 1 - di)) : 0.0f;
        v.z = (w0 + 2 >= di) ? __ldg(yr + (w0 + 2 - di)) : 0.0f;
        v.w = (w0 + 3 >= di) ? __ldg(yr + (w0 + 3 - di)) : 0.0f;
    }
    return v;
}

__global__ __launch_bounds__(256)
void cost_volume_kernel(const float* __restrict__ x,
                        const float* __restrict__ y,
                        float* __restrict__ out)
{
    unsigned int j0 = blockIdx.x * 1024u + threadIdx.x;

    float4 v0 = compute_elem(x, y, j0);
    float4 v1 = compute_elem(x, y, j0 + 256u);
    float4 v2 = compute_elem(x, y, j0 + 512u);
    float4 v3 = compute_elem(x, y, j0 + 768u);

    float4* o = reinterpret_cast<float4*>(out);
    __stwt(o + j0,        v0);
    __stwt(o + j0 + 256u, v1);
    __stwt(o + j0 + 512u, v2);
    __stwt(o + j0 + 768u, v3);
}

extern "C" void kernel_launch(void* const* d_in, const int* in_sizes, int n_in,
                              void* d_out, int out_size)
{
    const float* x = (const float*)d_in[0];
    const float* y = (const float*)d_in[1];
    float* out = (float*)d_out;

    cost_volume_kernel<<<TOTAL4 / 1024, 256>>>(x, y, out);
}